// round 9
// baseline (speedup 1.0000x reference)
#include <cuda_runtime.h>
#include <math.h>

#define S_LEN 60
#define D_IN  256
#define NHEAD 16
#define SC_STRIDE 68   // padded score row stride (floats)
#define V_BYTES (S_LEN * D_IN * 4)   // 61440

typedef unsigned long long u64;

__device__ __align__(16) float g_weff[NHEAD * D_IN];
__device__ float g_c[NHEAD];

__device__ __forceinline__ u64 fma2(u64 a, u64 b, u64 c) {
    u64 d;
    asm("fma.rn.f32x2 %0, %1, %2, %3;" : "=l"(d) : "l"(a), "l"(b), "l"(c));
    return d;
}
__device__ __forceinline__ u64 mul2(u64 a, u64 b) {
    u64 d;
    asm("mul.rn.f32x2 %0, %1, %2;" : "=l"(d) : "l"(a), "l"(b));
    return d;
}
__device__ __forceinline__ float sum2(u64 a) {
    float lo = __uint_as_float((unsigned)(a & 0xffffffffull));
    float hi = __uint_as_float((unsigned)(a >> 32));
    return lo + hi;
}
__device__ __forceinline__ u64 pack2(float lo, float hi) {
    u64 d;
    asm("mov.b64 %0, {%1, %2};" : "=l"(d) : "f"(lo), "f"(hi));
    return d;
}

// ---------------------------------------------------------------------------
// Fold Q into Wk:  w_eff[h][i] = (1/sqrt(dk)) * sum_d Q[h,d]*Wk[h*8+d, i]
// ---------------------------------------------------------------------------
__global__ void precompute_weff(const float* __restrict__ Q,
                                const float* __restrict__ Wk,
                                const float* __restrict__ bk) {
    const float inv_temp = 0.35355339059327373f;  // 1/sqrt(8)
    int i = threadIdx.x;  // 0..255
#pragma unroll
    for (int h = 0; h < NHEAD; ++h) {
        float s = 0.f;
#pragma unroll
        for (int d = 0; d < 8; ++d)
            s += Q[h * 8 + d] * Wk[(h * 8 + d) * D_IN + i];
        g_weff[h * D_IN + i] = s * inv_temp;
    }
    if (i < NHEAD) {
        float s = 0.f;
#pragma unroll
        for (int d = 0; d < 8; ++d)
            s += Q[i * 8 + d] * bk[i * 8 + d];
        g_c[i] = s * inv_temp;
    }
}

// ---------------------------------------------------------------------------
// Fused attention: one 512-thread CTA per batch element, 2 CTAs/SM.
// v staged via cp.async.bulk; scores split (head-half x k-half x s-group).
// ---------------------------------------------------------------------------
__global__ __launch_bounds__(512, 2)
void fused_attn_kernel(const float* __restrict__ v_g,
                       const unsigned char* __restrict__ pad_mask,
                       float* __restrict__ out_g,    // [B, 256]
                       float* __restrict__ attn_g,   // [H, B, S]
                       int B) {
    extern __shared__ float v_sm[];                   // 15360 floats
    __shared__ float sc_part[2][NHEAD][SC_STRIDE];    // k-half partial scores
    __shared__ float c_sm[NHEAD];
    __shared__ float part_sm[256];
    __shared__ __align__(8) u64 mbar;

    const int t = threadIdx.x;
    const int b = blockIdx.x;
    const int wid = t >> 5;        // 0..15
    const int lane = t & 31;

    const unsigned mb = (unsigned)__cvta_generic_to_shared(&mbar);

    // ---- mbarrier init + bulk copy of v (61440 B) ----
    if (t == 0)
        asm volatile("mbarrier.init.shared.b64 [%0], %1;" :: "r"(mb), "r"(1));
    __syncthreads();
    if (t == 0) {
        asm volatile("mbarrier.arrive.expect_tx.shared.b64 _, [%0], %1;"
                     :: "r"(mb), "r"(V_BYTES) : "memory");
        const unsigned dst = (unsigned)__cvta_generic_to_shared(v_sm);
        asm volatile(
            "cp.async.bulk.shared::cluster.global.mbarrier::complete_tx::bytes "
            "[%0], [%1], %2, [%3];"
            :: "r"(dst), "l"(v_g + (size_t)b * (S_LEN * D_IN)),
               "r"(V_BYTES), "r"(mb) : "memory");
    }

    // ---- w preload (overlaps bulk copy): 8 heads x k-half, 2 u64/head ----
    const int sg = wid & 3;        // s group: rows sg, sg+4, ... (15 rows)
    const int kh = (wid >> 2) & 1; // k half: floats [kh*128, kh*128+128)
    const int hh = wid >> 3;       // head half: h in [8*hh, 8*hh+8)
    u64 wx[8], wy[8];
    {
        const float4* wg4 = (const float4*)g_weff;   // 64 float4 per head row
#pragma unroll
        for (int j = 0; j < 8; ++j) {
            float4 f = __ldg(wg4 + (hh * 8 + j) * 64 + kh * 32 + lane);
            wx[j] = pack2(f.x, f.y);
            wy[j] = pack2(f.z, f.w);
        }
        if (t < NHEAD) c_sm[t] = g_c[t];
    }

    // ---- wait for v ----
    asm volatile(
        "{\n\t"
        ".reg .pred P;\n"
        "WAIT_%=:\n\t"
        "mbarrier.try_wait.parity.acquire.cta.shared::cta.b64 P, [%0], 0;\n\t"
        "@P bra DONE_%=;\n\t"
        "bra WAIT_%=;\n"
        "DONE_%=:\n\t"
        "}"
        :: "r"(mb) : "memory");

    // ---- Phase B: partial scores over this warp's k-half ----
    // Lane owns floats 4*(kh*32+lane) .. +3 of each row.
    {
        const bool hi4 = (lane & 16) != 0;
        const bool hi3 = (lane & 8) != 0;
        const bool hi2 = (lane & 4) != 0;
        const bool store_lane = (lane & 3) == 0;
        float* dst = &sc_part[kh][hh * 8 + (lane >> 2)][0];

        const ulonglong2* vb = (const ulonglong2*)v_sm + kh * 32 + lane;

#pragma unroll 3
        for (int r = sg; r < S_LEN; r += 4) {   // 15 rows per warp
            ulonglong2 vv = vb[(size_t)r * 64];
            float p[8];
#pragma unroll
            for (int j = 0; j < 8; ++j) {
                u64 a = mul2(vv.x, wx[j]);
                a = fma2(vv.y, wy[j], a);
                p[j] = sum2(a);
            }
            // value-halving tree: xor16 (4 shfl) -> xor8 (2) -> xor4 (1)
            float q[4];
#pragma unroll
            for (int j = 0; j < 4; ++j) {
                float mine = hi4 ? p[j + 4] : p[j];
                float send = hi4 ? p[j] : p[j + 4];
                q[j] = mine + __shfl_xor_sync(0xffffffffu, send, 16);
            }
            float r2[2];
#pragma unroll
            for (int j = 0; j < 2; ++j) {
                float mine = hi3 ? q[j + 2] : q[j];
                float send = hi3 ? q[j] : q[j + 2];
                r2[j] = mine + __shfl_xor_sync(0xffffffffu, send, 8);
            }
            float s;
            {
                float mine = hi2 ? r2[1] : r2[0];
                float send = hi2 ? r2[0] : r2[1];
                s = mine + __shfl_xor_sync(0xffffffffu, send, 4);
            }
            s += __shfl_xor_sync(0xffffffffu, s, 1);
            s += __shfl_xor_sync(0xffffffffu, s, 2);
            if (store_lane) dst[r] = s;
        }
    }
    __syncthreads();

    // ---- Phase C: combine k-halves, masked softmax, write attn ----
    {
        const unsigned char* pm = pad_mask + (size_t)b * S_LEN;
        const int h = wid;
        float x0 = sc_part[0][h][lane] + sc_part[1][h][lane] + c_sm[h];
        const bool has1 = (lane + 32) < S_LEN;
        float x1 = has1
            ? sc_part[0][h][lane + 32] + sc_part[1][h][lane + 32] + c_sm[h]
            : -1e30f;
        if (pm[lane]) x0 = -1e6f;
        if (has1 && pm[lane + 32]) x1 = -1e6f;

        float m = fmaxf(x0, x1);
#pragma unroll
        for (int o = 16; o > 0; o >>= 1)
            m = fmaxf(m, __shfl_xor_sync(0xffffffffu, m, o));

        float e0 = __expf(x0 - m);
        float e1 = has1 ? __expf(x1 - m) : 0.f;
        float ss = e0 + e1;
#pragma unroll
        for (int o = 16; o > 0; o >>= 1)
            ss += __shfl_xor_sync(0xffffffffu, ss, o);
        float inv = 1.0f / ss;

        float a0 = e0 * inv;
        float a1 = e1 * inv;
        sc_part[0][h][lane] = a0;
        if (has1) sc_part[0][h][lane + 32] = a1;

        float* ag = attn_g + ((size_t)h * B + b) * S_LEN;
        ag[lane] = a0;
        if (has1) ag[lane + 32] = a1;
    }
    __syncthreads();

    // ---- Phase D: out[b, h*16+d] = sum_s attn[h][s] * v[s][h*16+d] ----
    {
        const int tc = t & 255;        // output column
        const int half = t >> 8;       // 0: s 0..31, 1: s 32..59
        const int h = tc >> 4;
        const float4* a4 = (const float4*)(&sc_part[0][h][0]);
        const float* vc = v_sm + tc;
        float acc = 0.f;
        if (half == 0) {
#pragma unroll
            for (int q = 0; q < 8; ++q) {
                float4 a = a4[q];
                const float* vr = vc + (q * 4) * D_IN;
                acc += a.x * vr[0];
                acc += a.y * vr[D_IN];
                acc += a.z * vr[2 * D_IN];
                acc += a.w * vr[3 * D_IN];
            }
        } else {
#pragma unroll
            for (int q = 8; q < 15; ++q) {
                float4 a = a4[q];
                const float* vr = vc + (q * 4) * D_IN;
                acc += a.x * vr[0];
                acc += a.y * vr[D_IN];
                acc += a.z * vr[2 * D_IN];
                acc += a.w * vr[3 * D_IN];
            }
            part_sm[tc] = acc;
        }
        __syncthreads();
        if (half == 0)
            out_g[(size_t)b * D_IN + tc] = acc + part_sm[tc];
    }
}

// ---------------------------------------------------------------------------
extern "C" void kernel_launch(void* const* d_in, const int* in_sizes, int n_in,
                              void* d_out, int out_size) {
    const float* v = (const float*)d_in[0];
    const float* Q = (const float*)d_in[1];
    const float* Wk = (const float*)d_in[2];
    const float* bk = (const float*)d_in[3];
    const unsigned char* pm = (const unsigned char*)d_in[4];

    const int B = in_sizes[0] / (S_LEN * D_IN);

    float* out = (float*)d_out;                  // [B, 256]
    float* attn = out + (size_t)B * D_IN;        // [H, B, S]

    precompute_weff<<<1, 256>>>(Q, Wk, bk);

    const size_t smem_bytes = (size_t)(S_LEN * D_IN) * sizeof(float);
    cudaFuncSetAttribute(fused_attn_kernel,
                         cudaFuncAttributeMaxDynamicSharedMemorySize,
                         (int)smem_bytes);

    fused_attn_kernel<<<B, 512, smem_bytes>>>(v, pm, out, attn, B);
}

// round 10
// speedup vs baseline: 1.1489x; 1.1489x over previous
#include <cuda_runtime.h>
#include <math.h>

#define S_LEN 60
#define D_IN  256
#define NHEAD 16
#define SC_STRIDE 68   // padded score row stride (floats)
#define V_BYTES (S_LEN * D_IN * 4)   // 61440

typedef unsigned long long u64;

__device__ __align__(16) float g_weff[NHEAD * D_IN];
__device__ float g_c[NHEAD];

__device__ __forceinline__ u64 fma2(u64 a, u64 b, u64 c) {
    u64 d;
    asm("fma.rn.f32x2 %0, %1, %2, %3;" : "=l"(d) : "l"(a), "l"(b), "l"(c));
    return d;
}
__device__ __forceinline__ u64 mul2(u64 a, u64 b) {
    u64 d;
    asm("mul.rn.f32x2 %0, %1, %2;" : "=l"(d) : "l"(a), "l"(b));
    return d;
}
__device__ __forceinline__ float sum2(u64 a) {
    float lo = __uint_as_float((unsigned)(a & 0xffffffffull));
    float hi = __uint_as_float((unsigned)(a >> 32));
    return lo + hi;
}
__device__ __forceinline__ u64 pack2(float lo, float hi) {
    u64 d;
    asm("mov.b64 %0, {%1, %2};" : "=l"(d) : "f"(lo), "f"(hi));
    return d;
}

// ---------------------------------------------------------------------------
// Fold Q into Wk:  w_eff[h][i] = (1/sqrt(dk)) * sum_d Q[h,d]*Wk[h*8+d, i]
// ---------------------------------------------------------------------------
__global__ void precompute_weff(const float* __restrict__ Q,
                                const float* __restrict__ Wk,
                                const float* __restrict__ bk) {
    const float inv_temp = 0.35355339059327373f;  // 1/sqrt(8)
    int i = threadIdx.x;  // 0..255
#pragma unroll
    for (int h = 0; h < NHEAD; ++h) {
        float s = 0.f;
#pragma unroll
        for (int d = 0; d < 8; ++d)
            s += Q[h * 8 + d] * Wk[(h * 8 + d) * D_IN + i];
        g_weff[h * D_IN + i] = s * inv_temp;
    }
    if (i < NHEAD) {
        float s = 0.f;
#pragma unroll
        for (int d = 0; d < 8; ++d)
            s += Q[i * 8 + d] * bk[i * 8 + d];
        g_c[i] = s * inv_temp;
    }
}

// ---------------------------------------------------------------------------
// Fused attention: one 512-thread CTA per batch element, 2 CTAs/SM.
// Warp = (head-quarter, s-group): 4 heads, full 256-k rows.
// ---------------------------------------------------------------------------
__global__ __launch_bounds__(512, 2)
void fused_attn_kernel(const float* __restrict__ v_g,
                       const unsigned char* __restrict__ pad_mask,
                       float* __restrict__ out_g,    // [B, 256]
                       float* __restrict__ attn_g,   // [H, B, S]
                       int B) {
    extern __shared__ float v_sm[];                   // 15360 floats
    __shared__ float sc_sm[NHEAD][SC_STRIDE];
    __shared__ float c_sm[NHEAD];
    __shared__ float part_sm[256];
    __shared__ __align__(8) u64 mbar;

    const int t = threadIdx.x;
    const int b = blockIdx.x;
    const int wid = t >> 5;        // 0..15
    const int lane = t & 31;

    const unsigned mb = (unsigned)__cvta_generic_to_shared(&mbar);

    // ---- mbarrier init + bulk copy of v (61440 B) ----
    if (t == 0)
        asm volatile("mbarrier.init.shared.b64 [%0], %1;" :: "r"(mb), "r"(1));
    __syncthreads();
    if (t == 0) {
        asm volatile("mbarrier.arrive.expect_tx.shared.b64 _, [%0], %1;"
                     :: "r"(mb), "r"(V_BYTES) : "memory");
        const unsigned dst = (unsigned)__cvta_generic_to_shared(v_sm);
        asm volatile(
            "cp.async.bulk.shared::cluster.global.mbarrier::complete_tx::bytes "
            "[%0], [%1], %2, [%3];"
            :: "r"(dst), "l"(v_g + (size_t)b * (S_LEN * D_IN)),
               "r"(V_BYTES), "r"(mb) : "memory");
    }

    // ---- w preload (overlaps copy): 4 heads, full row, 4 u64 per head/lane ----
    const int hq = wid & 3;        // head quarter: h in [4*hq, 4*hq+4)
    const int sq = wid >> 2;       // s group: rows sq, sq+4, ... (15 rows)
    u64 w0x[4], w0y[4], w1x[4], w1y[4];
    {
        const float4* wg4 = (const float4*)g_weff;   // 64 float4 per head row
#pragma unroll
        for (int j = 0; j < 4; ++j) {
            int h = hq * 4 + j;
            float4 a = __ldg(wg4 + h * 64 + lane);        // floats 4l..4l+3
            float4 c = __ldg(wg4 + h * 64 + 32 + lane);   // floats 128+4l..
            w0x[j] = pack2(a.x, a.y);
            w0y[j] = pack2(a.z, a.w);
            w1x[j] = pack2(c.x, c.y);
            w1y[j] = pack2(c.z, c.w);
        }
        if (t < NHEAD) c_sm[t] = g_c[t];
    }

    // ---- wait for v ----
    asm volatile(
        "{\n\t"
        ".reg .pred P;\n"
        "WAIT_%=:\n\t"
        "mbarrier.try_wait.parity.acquire.cta.shared::cta.b64 P, [%0], 0;\n\t"
        "@P bra DONE_%=;\n\t"
        "bra WAIT_%=;\n"
        "DONE_%=:\n\t"
        "}"
        :: "r"(mb) : "memory");

    // ---- Phase B: scores[h][s] = w_eff[h] . v[s] (c added in Phase C) ----
    // Lane owns floats {4l..4l+3, 128+4l..131+4l} of each row.
    {
        const bool hi4 = (lane & 16) != 0;
        const bool hi3 = (lane & 8) != 0;
        const bool store_lane = (lane & 7) == 0;
        float* dst = &sc_sm[hq * 4 + (lane >> 3)][0];

        const ulonglong2* vb = (const ulonglong2*)v_sm + lane;

#pragma unroll 5
        for (int r = sq; r < S_LEN; r += 4) {   // 15 rows per warp
            const ulonglong2* vr = vb + (size_t)r * 64;
            ulonglong2 v0 = vr[0];     // floats 4l..4l+3
            ulonglong2 v1 = vr[32];    // floats 128+4l..131+4l
            float p[4];
#pragma unroll
            for (int j = 0; j < 4; ++j) {
                u64 a = mul2(v0.x, w0x[j]);
                a = fma2(v0.y, w0y[j], a);
                a = fma2(v1.x, w1x[j], a);
                a = fma2(v1.y, w1y[j], a);
                p[j] = sum2(a);
            }
            // value-halving: xor16 (2 shfl) -> xor8 (1) -> oct butterflies (3)
            float q0, q1;
            {
                float m0 = hi4 ? p[2] : p[0];
                float s0 = hi4 ? p[0] : p[2];
                float m1 = hi4 ? p[3] : p[1];
                float s1 = hi4 ? p[1] : p[3];
                q0 = m0 + __shfl_xor_sync(0xffffffffu, s0, 16);
                q1 = m1 + __shfl_xor_sync(0xffffffffu, s1, 16);
            }
            float s;
            {
                float mine = hi3 ? q1 : q0;
                float send = hi3 ? q0 : q1;
                s = mine + __shfl_xor_sync(0xffffffffu, send, 8);
            }
            s += __shfl_xor_sync(0xffffffffu, s, 1);
            s += __shfl_xor_sync(0xffffffffu, s, 2);
            s += __shfl_xor_sync(0xffffffffu, s, 4);
            if (store_lane) dst[r] = s;
        }
    }
    __syncthreads();

    // ---- Phase C: masked softmax over s (one head per warp), write attn ----
    {
        const unsigned char* pm = pad_mask + (size_t)b * S_LEN;
        const int h = wid;
        const float c_h = c_sm[h];
        float x0 = sc_sm[h][lane] + c_h;
        const bool has1 = (lane + 32) < S_LEN;
        float x1 = has1 ? sc_sm[h][lane + 32] + c_h : -1e30f;
        if (pm[lane]) x0 = -1e6f;
        if (has1 && pm[lane + 32]) x1 = -1e6f;

        float m = fmaxf(x0, x1);
#pragma unroll
        for (int o = 16; o > 0; o >>= 1)
            m = fmaxf(m, __shfl_xor_sync(0xffffffffu, m, o));

        float e0 = __expf(x0 - m);
        float e1 = has1 ? __expf(x1 - m) : 0.f;
        float ss = e0 + e1;
#pragma unroll
        for (int o = 16; o > 0; o >>= 1)
            ss += __shfl_xor_sync(0xffffffffu, ss, o);
        float inv = 1.0f / ss;

        float a0 = e0 * inv;
        float a1 = e1 * inv;
        sc_sm[h][lane] = a0;
        if (has1) sc_sm[h][lane + 32] = a1;

        float* ag = attn_g + ((size_t)h * B + b) * S_LEN;
        ag[lane] = a0;
        if (has1) ag[lane + 32] = a1;
    }
    __syncthreads();

    // ---- Phase D: out[b, h*16+d] = sum_s attn[h][s] * v[s][h*16+d] ----
    // Split s-range across the two 256-thread halves; combine via smem.
    {
        const int tc = t & 255;        // output column
        const int half = t >> 8;       // 0: s 0..31, 1: s 32..59
        const int h = tc >> 4;
        const float4* a4 = (const float4*)(&sc_sm[h][0]);
        const float* vc = v_sm + tc;
        float acc = 0.f;
        if (half == 0) {
#pragma unroll
            for (int q = 0; q < 8; ++q) {
                float4 a = a4[q];
                const float* vr = vc + (q * 4) * D_IN;
                acc += a.x * vr[0];
                acc += a.y * vr[D_IN];
                acc += a.z * vr[2 * D_IN];
                acc += a.w * vr[3 * D_IN];
            }
        } else {
#pragma unroll
            for (int q = 8; q < 15; ++q) {
                float4 a = a4[q];
                const float* vr = vc + (q * 4) * D_IN;
                acc += a.x * vr[0];
                acc += a.y * vr[D_IN];
                acc += a.z * vr[2 * D_IN];
                acc += a.w * vr[3 * D_IN];
            }
            part_sm[tc] = acc;
        }
        __syncthreads();
        if (half == 0)
            out_g[(size_t)b * D_IN + tc] = acc + part_sm[tc];
    }
}

// ---------------------------------------------------------------------------
extern "C" void kernel_launch(void* const* d_in, const int* in_sizes, int n_in,
                              void* d_out, int out_size) {
    const float* v = (const float*)d_in[0];
    const float* Q = (const float*)d_in[1];
    const float* Wk = (const float*)d_in[2];
    const float* bk = (const float*)d_in[3];
    const unsigned char* pm = (const unsigned char*)d_in[4];

    const int B = in_sizes[0] / (S_LEN * D_IN);

    float* out = (float*)d_out;                  // [B, 256]
    float* attn = out + (size_t)B * D_IN;        // [H, B, S]

    precompute_weff<<<1, 256>>>(Q, Wk, bk);

    const size_t smem_bytes = (size_t)(S_LEN * D_IN) * sizeof(float);
    cudaFuncSetAttribute(fused_attn_kernel,
                         cudaFuncAttributeMaxDynamicSharedMemorySize,
                         (int)smem_bytes);

    fused_attn_kernel<<<B, 512, smem_bytes>>>(v, pm, out, attn, B);
}